// round 11
// baseline (speedup 1.0000x reference)
#include <cuda_runtime.h>
#include <cuda_fp16.h>
#include <math.h>
#include <stdint.h>

#define NT    2048      // B*T
#define CDIM  384
#define TDIM  32
#define NHEAD 6
#define HEADD 64
#define VOCABSZ 50257
#define TILE_M 256
#define TILE_N 128
#define NMB   8         // NT/256
#define NNB   393       // ceil(VOCAB/128)
#define NCB   786       // stats blocks of 64 cols (2 per CTA N-tile)
#define KCH   32
#define NCHUNK 12       // 384/32
#define CHUNK_AU 4096   // u32 per permuted A chunk (256 x 32 fp16)
#define CHUNK_BU 2048   // u32 per permuted B chunk (128 x 32 fp16)
#define NSTAGE 3
#define STAGE_BYTES 24576   // A 16K + B 8K
#define QKV_MAT_U (3 * NCHUNK * CHUNK_BU)

// ---- scratch ----
__device__ float g_h[NT * CDIM];
__device__ float g_q[NT * CDIM];
__device__ float g_k[NT * CDIM];
__device__ float g_v[NT * CDIM];
__device__ float g_pmax[NT * NCB];
__device__ float g_psum[NT * NCB];
__device__ float g_rowloss[NT];
__device__ uint32_t g_aperm[NMB * NCHUNK * CHUNK_AU];      // 1.5 MB
__device__ uint32_t g_blm[NNB * NCHUNK * CHUNK_BU];        // 38.6 MB
__device__ uint32_t g_bqkv[2 * 3 * QKV_MAT_U];             // 1.7 MB

// =========================================================================
// helpers
// =========================================================================
__device__ __forceinline__ uint32_t smem_u32(const void* p) {
    uint32_t a;
    asm("{ .reg .u64 t; cvta.to.shared.u64 t, %1; cvt.u32.u64 %0, t; }" : "=r"(a) : "l"(p));
    return a;
}
__device__ __forceinline__ uint32_t packh2(float x, float y) {
    __half2 h = __floats2half2_rn(x, y);
    return *(uint32_t*)&h;
}
__device__ __forceinline__ void mma_f16(float c[4], const uint32_t a[4], const uint32_t b[2]) {
    asm volatile(
        "mma.sync.aligned.m16n8k16.row.col.f32.f16.f16.f32 "
        "{%0,%1,%2,%3}, {%4,%5,%6,%7}, {%8,%9}, {%0,%1,%2,%3};"
        : "+f"(c[0]), "+f"(c[1]), "+f"(c[2]), "+f"(c[3])
        : "r"(a[0]), "r"(a[1]), "r"(a[2]), "r"(a[3]), "r"(b[0]), "r"(b[1]));
}
#define LDS128(r, addr) \
    asm volatile("ld.shared.v4.b32 {%0,%1,%2,%3}, [%4];" \
        : "=r"((r)[0]), "=r"((r)[1]), "=r"((r)[2]), "=r"((r)[3]) : "r"(addr))
#define LDS64(r, addr) \
    asm volatile("ld.shared.v2.b32 {%0,%1}, [%2];" \
        : "=r"((r)[0]), "=r"((r)[1]) : "r"(addr))
#define CP_ASYNC16(dst, src) \
    asm volatile("cp.async.cg.shared.global [%0], [%1], 16;" :: "r"(dst), "l"(src) : "memory")
#define CP_COMMIT() asm volatile("cp.async.commit_group;" ::: "memory")
#define CP_WAIT1()  asm volatile("cp.async.wait_group 1;" ::: "memory")

// SMEM: bias[128] @0 ; 3 stages of 24KB @1024 ; epilogue stage (128x132 f32) reuses
#define SM_STAGE0 1024
#define SM_TOTAL  (1024 + NSTAGE * STAGE_BYTES)   // 74752

// fp16 fragment-permuted layouts within a chunk (m16n8k16), k0 = even k:
//  A (256 rows): s=k0>>4, mb=m>>4 (0..15), lane=(m&7)*4+((k0>>1)&3),
//    reg=((m>>3)&1)+2*((k0>>3)&1);  u32 idx = ((s*16+mb)*32+lane)*4+reg
//  B (128 rows): s=k0>>4, nb=n>>3 (0..15), lane=(n&7)*4+((k0>>1)&3),
//    reg=(k0>>3)&1;                 u32 idx = ((s*16+nb)*32+lane)*2+reg

__device__ __forceinline__ void compute_chunk(uint32_t Abuf, uint32_t Bbuf,
                                              int wm, int wn, int lid,
                                              float c[2][8][4]) {
#pragma unroll
    for (int ks = 0; ks < 2; ks++) {
        uint32_t a[2][4];
#pragma unroll
        for (int r = 0; r < 2; r++)
            LDS128(a[r], Abuf + ((ks * 16 + wm * 2 + r) * 32 + lid) * 16);
        uint32_t b[8][2];
#pragma unroll
        for (int nf = 0; nf < 8; nf++)
            LDS64(b[nf], Bbuf + ((ks * 16 + wn * 8 + nf) * 32 + lid) * 8);
#pragma unroll
        for (int r = 0; r < 2; r++)
#pragma unroll
            for (int nf = 0; nf < 8; nf++)
                mma_f16(c[r][nf], a[r], b[nf]);
    }
}

__device__ __forceinline__ void supd(float& m, float& s, float v) {
    if (v > m) { s = s * __expf(m - v) + 1.f; m = v; }
    else       { s += __expf(v - m); }
}

// =========================================================================
// Permutation kernels (global fp32 -> fp16 fragment-permuted global)
// =========================================================================
__global__ void aperm_kernel(const float* __restrict__ A) {
    __shared__ uint32_t sbuf[CHUNK_AU];
    const int tid = threadIdx.x;
    const int mb = blockIdx.x, kc = blockIdx.y;
    const int rb = tid >> 3, j = tid & 7;
    const float* Ag = A + (size_t)(mb * TILE_M) * CDIM + kc * KCH + j * 4;
#pragma unroll
    for (int i = 0; i < 8; i++) {
        int r = i * 32 + rb;
        float4 v = *(const float4*)(Ag + (size_t)r * CDIM);
#pragma unroll
        for (int p = 0; p < 2; p++) {
            int k0 = j * 4 + 2 * p;
            int s = k0 >> 4;
            int lane = (r & 7) * 4 + ((k0 >> 1) & 3);
            int reg = ((r >> 3) & 1) + 2 * ((k0 >> 3) & 1);
            int idx = ((s * 16 + (r >> 4)) * 32 + lane) * 4 + reg;
            sbuf[idx] = packh2(p ? v.z : v.x, p ? v.w : v.y);
        }
    }
    __syncthreads();
    uint32_t* out = g_aperm + ((size_t)mb * NCHUNK + kc) * CHUNK_AU;
#pragma unroll
    for (int i = 0; i < 4; i++)
        *(uint4*)(out + i * 1024 + tid * 4) = *(const uint4*)&sbuf[i * 1024 + tid * 4];
}

__global__ void bperm_kernel(const float* __restrict__ B0, const float* __restrict__ B1,
                             const float* __restrict__ B2,
                             uint32_t* __restrict__ O0, uint32_t* __restrict__ O1,
                             uint32_t* __restrict__ O2, int Ntot) {
    __shared__ uint32_t sbuf[CHUNK_BU];
    const int tid = threadIdx.x;
    const int nb = blockIdx.x, kc = blockIdx.y, z = blockIdx.z;
    const float* B = (z == 0) ? B0 : (z == 1 ? B1 : B2);
    uint32_t* O = (z == 0) ? O0 : (z == 1 ? O1 : O2);
    const int rb = tid >> 3, j = tid & 7;
#pragma unroll
    for (int i = 0; i < 4; i++) {
        int r = i * 32 + rb;
        int n = nb * 128 + r;
        float4 v = (n < Ntot) ? *(const float4*)(B + (size_t)n * CDIM + kc * KCH + j * 4)
                              : make_float4(0.f, 0.f, 0.f, 0.f);
#pragma unroll
        for (int p = 0; p < 2; p++) {
            int k0 = j * 4 + 2 * p;
            int s = k0 >> 4;
            int lane = (r & 7) * 4 + ((k0 >> 1) & 3);
            int reg = (k0 >> 3) & 1;
            int idx = ((s * 16 + (r >> 3)) * 32 + lane) * 2 + reg;
            sbuf[idx] = packh2(p ? v.z : v.x, p ? v.w : v.y);
        }
    }
    __syncthreads();
    uint32_t* out = O + ((size_t)nb * NCHUNK + kc) * CHUNK_BU;
#pragma unroll
    for (int i = 0; i < 2; i++)
        *(uint4*)(out + i * 1024 + tid * 4) = *(const uint4*)&sbuf[i * 1024 + tid * 4];
}

// =========================================================================
// fp16 tensor GEMM, 256x128 tile, 512 threads (16 warps: wm 0..7, wn 0..1).
// grid: (NMB, Nblocks, nz); z selects B/C pair (fused QKV). A = g_aperm.
// =========================================================================
template <bool STATS>
__global__ __launch_bounds__(512)
void mma_gemm(const uint32_t* __restrict__ Bp0, const uint32_t* __restrict__ Bp1,
              const uint32_t* __restrict__ Bp2,
              float* __restrict__ C0, float* __restrict__ C1, float* __restrict__ C2,
              const float* __restrict__ bias, int Ntot) {
    extern __shared__ __align__(1024) char smem[];
    const int tid = threadIdx.x;
    const int lid = tid & 31, wid = tid >> 5;
    const int wm = wid >> 1, wn = wid & 1;
    const int bm = blockIdx.x * TILE_M;
    const int bn = blockIdx.y * TILE_N;
    const uint32_t* Bperm = (blockIdx.z == 0) ? Bp0 : (blockIdx.z == 1 ? Bp1 : Bp2);
    float* C = (blockIdx.z == 0) ? C0 : (blockIdx.z == 1 ? C1 : C2);

    const uint32_t* Ac = g_aperm + (size_t)blockIdx.x * NCHUNK * CHUNK_AU;
    const uint32_t* Bc = Bperm + (size_t)blockIdx.y * NCHUNK * CHUNK_BU;

    float* biasS = (float*)smem;
    float* stage = (float*)(smem + SM_STAGE0);
    const uint32_t sb = smem_u32(smem);

    if (tid < TILE_N) {
        int n = bn + tid;
        biasS[tid] = (bias != nullptr && n < Ntot) ? bias[n] : 0.f;
    }

    float c[2][8][4];
#pragma unroll
    for (int r = 0; r < 2; r++)
#pragma unroll
        for (int nf = 0; nf < 8; nf++)
#pragma unroll
            for (int e = 0; e < 4; e++) c[r][nf][e] = 0.f;

    // ---- cp.async copy of one 24KB chunk (A 16K + B 8K) into stage s ----
    // A: 1024 uint4, threads copy [tid] and [tid+512]; B: 512 uint4, [tid] (tid<512)
    auto issue = [&](int kcc, int s) {
        uint32_t dA = sb + SM_STAGE0 + s * STAGE_BYTES;
        uint32_t dB = dA + 16384;
        const uint32_t* srcA = Ac + (size_t)kcc * CHUNK_AU;
        const uint32_t* srcB = Bc + (size_t)kcc * CHUNK_BU;
        CP_ASYNC16(dA + tid * 16, srcA + tid * 4);
        CP_ASYNC16(dA + (tid + 512) * 16, srcA + (tid + 512) * 4);
        if (tid < 512) CP_ASYNC16(dB + tid * 16, srcB + tid * 4);
    };

    issue(0, 0); CP_COMMIT();
    issue(1, 1); CP_COMMIT();

    for (int kc = 0; kc < NCHUNK; kc++) {
        CP_WAIT1();
        __syncthreads();                 // chunk kc visible; stage (kc+2)%3 free
        if (kc + 2 < NCHUNK) issue(kc + 2, (kc + 2) % NSTAGE);
        CP_COMMIT();
        const uint32_t base = sb + SM_STAGE0 + (kc % NSTAGE) * STAGE_BYTES;
        compute_chunk(base, base + 16384, wm, wn, lid, c);
    }

    // ---- epilogue ----
    const int g = lid >> 2, t4 = lid & 3;

    // fold bias into accumulators
#pragma unroll
    for (int r = 0; r < 2; r++)
#pragma unroll
        for (int nf = 0; nf < 8; nf++) {
            const int col = wn * 64 + nf * 8 + t4 * 2;
            const float b0 = biasS[col], b1 = biasS[col + 1];
            c[r][nf][0] += b0; c[r][nf][1] += b1;
            c[r][nf][2] += b0; c[r][nf][3] += b1;
        }

    if (STATS) {
        float rm[2][2], rs[2][2];
#pragma unroll
        for (int r = 0; r < 2; r++)
#pragma unroll
            for (int h = 0; h < 2; h++) { rm[r][h] = -INFINITY; rs[r][h] = 0.f; }
#pragma unroll
        for (int r = 0; r < 2; r++)
#pragma unroll
            for (int nf = 0; nf < 8; nf++) {
                const int n = bn + wn * 64 + nf * 8 + t4 * 2;
                if (n < Ntot)     { supd(rm[r][0], rs[r][0], c[r][nf][0]);
                                    supd(rm[r][1], rs[r][1], c[r][nf][2]); }
                if (n + 1 < Ntot) { supd(rm[r][0], rs[r][0], c[r][nf][1]);
                                    supd(rm[r][1], rs[r][1], c[r][nf][3]); }
            }
#pragma unroll
        for (int r = 0; r < 2; r++)
#pragma unroll
            for (int h = 0; h < 2; h++) {
                float m = rm[r][h], s = rs[r][h];
#pragma unroll
                for (int off = 1; off <= 2; off <<= 1) {
                    float om = __shfl_xor_sync(0xffffffffu, m, off);
                    float os = __shfl_xor_sync(0xffffffffu, s, off);
                    float M = fmaxf(m, om);
                    float S = ((m > -INFINITY) ? s * __expf(m - M) : 0.f) +
                              ((om > -INFINITY) ? os * __expf(om - M) : 0.f);
                    m = M; s = S;
                }
                if (t4 == 0) {
                    int mrow = bm + wm * 32 + r * 16 + h * 8 + g;
                    size_t idx = (size_t)mrow * NCB + blockIdx.y * 2 + wn;
                    g_pmax[idx] = m;
                    g_psum[idx] = s;
                }
            }
    }

    // staged coalesced store, two 128-row halves through one 128x132 buffer
#pragma unroll
    for (int half = 0; half < 2; half++) {
        __syncthreads();                 // mainloop done / prior half stored
        if ((wm >> 2) == half) {
            const int lbase = (wm & 3) * 32;
#pragma unroll
            for (int r = 0; r < 2; r++)
#pragma unroll
                for (int nf = 0; nf < 8; nf++) {
                    const int col = wn * 64 + nf * 8 + t4 * 2;
                    const int lrow = lbase + r * 16 + g;
                    *(float2*)&stage[lrow * 132 + col] =
                        make_float2(c[r][nf][0], c[r][nf][1]);
                    *(float2*)&stage[(lrow + 8) * 132 + col] =
                        make_float2(c[r][nf][2], c[r][nf][3]);
                }
        }
        __syncthreads();
#pragma unroll 8
        for (int it = 0; it < 32; it++) {
            int idx = it * 512 + tid;
            int rr = idx >> 7, cc = idx & 127;
            int n = bn + cc;
            if (n < Ntot)
                C[(size_t)(bm + half * 128 + rr) * Ntot + n] = stage[rr * 132 + cc];
        }
    }
}

// =========================================================================
// Embedding
// =========================================================================
__global__ void embed_kernel(const int* __restrict__ x,
                             const float* __restrict__ w_e,
                             const float* __restrict__ pos) {
    int idx = blockIdx.x * blockDim.x + threadIdx.x;
    if (idx >= NT * CDIM) return;
    int bt = idx / CDIM, c = idx % CDIM;
    int tok = x[bt];
    g_h[idx] = w_e[(size_t)tok * CDIM + c] + pos[(bt % TDIM) * CDIM + c];
}

// =========================================================================
// Attention (T=32, D=64, causal, h += attn)
// =========================================================================
__global__ void attn_kernel() {
    __shared__ float qs[32][65];
    __shared__ float ks[32][65];
    __shared__ float vs[32][65];
    __shared__ float w[32][33];

    const int bh = blockIdx.x;
    const int b = bh / NHEAD, hd = bh % NHEAD;
    const int tid = threadIdx.x;
    const int base = (b * TDIM) * CDIM + hd * HEADD;

    for (int i = tid; i < 32 * 64; i += 256) {
        int t = i >> 6, d = i & 63;
        int g = base + t * CDIM + d;
        qs[t][d] = g_q[g];
        ks[t][d] = g_k[g];
        vs[t][d] = g_v[g];
    }
    __syncthreads();

    const float scale = 0.125f;
    for (int i = tid; i < 32 * 32; i += 256) {
        int t = i >> 5, s = i & 31;
        float v = -INFINITY;
        if (s <= t) {
            float acc = 0.f;
#pragma unroll
            for (int d = 0; d < 64; d++) acc += qs[t][d] * ks[s][d];
            v = acc * scale;
        }
        w[t][s] = v;
    }
    __syncthreads();

    if (tid < 32) {
        int t = tid;
        float mx = -INFINITY;
        for (int s = 0; s <= t; s++) mx = fmaxf(mx, w[t][s]);
        float sum = 0.f;
        for (int s = 0; s <= t; s++) { float e = expf(w[t][s] - mx); w[t][s] = e; sum += e; }
        float inv = 1.f / sum;
        for (int s = 0; s <= t; s++) w[t][s] *= inv;
        for (int s = t + 1; s < 32; s++) w[t][s] = 0.f;
    }
    __syncthreads();

    for (int i = tid; i < 32 * 64; i += 256) {
        int t = i >> 6, d = i & 63;
        float acc = 0.f;
#pragma unroll
        for (int s = 0; s < 32; s++) acc += w[t][s] * vs[s][d];
        g_h[base + t * CDIM + d] += acc;
    }
}

// =========================================================================
// Loss
// =========================================================================
__global__ void loss_rows_kernel(const float* __restrict__ logits,
                                 const int* __restrict__ targets) {
    const int row = blockIdx.x;
    const int tid = threadIdx.x;
    float m = -INFINITY, s = 0.f;
    for (int cb = tid; cb < NCB; cb += 256) {
        float mi = g_pmax[(size_t)row * NCB + cb];
        float si = g_psum[(size_t)row * NCB + cb];
        if (mi > m) { s = s * expf(m - mi) + si; m = mi; }
        else if (mi > -INFINITY) { s += si * expf(mi - m); }
    }
    __shared__ float sm[256], ss[256];
    sm[tid] = m; ss[tid] = s;
    __syncthreads();
    for (int st = 128; st > 0; st >>= 1) {
        if (tid < st) {
            float m1 = sm[tid], s1 = ss[tid];
            float m2 = sm[tid + st], s2 = ss[tid + st];
            float M = fmaxf(m1, m2);
            float S = ((m1 > -INFINITY) ? s1 * expf(m1 - M) : 0.f) +
                      ((m2 > -INFINITY) ? s2 * expf(m2 - M) : 0.f);
            sm[tid] = M; ss[tid] = S;
        }
        __syncthreads();
    }
    if (tid == 0) {
        float logZ = sm[0] + logf(ss[0]);
        int t = targets[row];
        float lt = logits[(size_t)row * VOCABSZ + t];
        g_rowloss[row] = logZ - lt;
    }
}

__global__ void loss_final_kernel(float* __restrict__ out, int out_size) {
    __shared__ float sm[256];
    const int tid = threadIdx.x;
    float s = 0.f;
    for (int r = tid; r < NT; r += 256) s += g_rowloss[r];
    sm[tid] = s;
    __syncthreads();
    for (int st = 128; st > 0; st >>= 1) {
        if (tid < st) sm[tid] += sm[tid + st];
        __syncthreads();
    }
    if (tid == 0) {
        float loss = sm[0] / (float)NT;
        size_t logits_elems = (size_t)NT * VOCABSZ;
        if ((size_t)out_size > logits_elems) out[logits_elems] = loss;
    }
}

// =========================================================================
extern "C" void kernel_launch(void* const* d_in, const int* in_sizes, int n_in,
                              void* d_out, int out_size) {
    const int*   x       = (const int*)d_in[0];
    const int*   targets = (const int*)d_in[1];
    const float* w_e     = (const float*)d_in[2];
    const float* pos     = (const float*)d_in[3];
    const float* Wq      = (const float*)d_in[4];
    const float* Wk      = (const float*)d_in[5];
    const float* Wv      = (const float*)d_in[6];
    const float* lm_w    = (const float*)d_in[7];
    const float* lm_b    = (const float*)d_in[8];
    float* out = (float*)d_out;

    float *ph, *pq, *pk, *pv;
    uint32_t *pblm, *pbqkv;
    cudaGetSymbolAddress((void**)&ph, g_h);
    cudaGetSymbolAddress((void**)&pq, g_q);
    cudaGetSymbolAddress((void**)&pk, g_k);
    cudaGetSymbolAddress((void**)&pv, g_v);
    cudaGetSymbolAddress((void**)&pblm, g_blm);
    cudaGetSymbolAddress((void**)&pbqkv, g_bqkv);

    cudaFuncSetAttribute(mma_gemm<false>, cudaFuncAttributeMaxDynamicSharedMemorySize, SM_TOTAL);
    cudaFuncSetAttribute(mma_gemm<true>,  cudaFuncAttributeMaxDynamicSharedMemorySize, SM_TOTAL);

    embed_kernel<<<(NT * CDIM + 255) / 256, 256>>>(x, w_e, pos);

    const size_t wstride = (size_t)NHEAD * HEADD * CDIM;
    // permute all weights (lm_w + 2 layers of Q/K/V)
    bperm_kernel<<<dim3(NNB, NCHUNK, 1), 256>>>(lm_w, lm_w, lm_w, pblm, pblm, pblm, VOCABSZ);
    for (int l = 0; l < 2; l++) {
        uint32_t* bq = pbqkv + (size_t)(l * 3 + 0) * QKV_MAT_U;
        uint32_t* bk = pbqkv + (size_t)(l * 3 + 1) * QKV_MAT_U;
        uint32_t* bv = pbqkv + (size_t)(l * 3 + 2) * QKV_MAT_U;
        bperm_kernel<<<dim3(3, NCHUNK, 3), 256>>>(
            Wq + l * wstride, Wk + l * wstride, Wv + l * wstride, bq, bk, bv, CDIM);
    }

    for (int l = 0; l < 2; l++) {
        uint32_t* bq = pbqkv + (size_t)(l * 3 + 0) * QKV_MAT_U;
        uint32_t* bk = pbqkv + (size_t)(l * 3 + 1) * QKV_MAT_U;
        uint32_t* bv = pbqkv + (size_t)(l * 3 + 2) * QKV_MAT_U;
        aperm_kernel<<<dim3(NMB, NCHUNK), 256>>>(ph);
        mma_gemm<false><<<dim3(NMB, 3, 3), 512, SM_TOTAL>>>(
            bq, bk, bv, pq, pk, pv, nullptr, CDIM);
        attn_kernel<<<(NT / TDIM) * NHEAD, 256>>>();
    }

    aperm_kernel<<<dim3(NMB, NCHUNK), 256>>>(ph);
    mma_gemm<true><<<dim3(NMB, NNB, 1), 512, SM_TOTAL>>>(
        pblm, pblm, pblm, out, out, out, lm_b, VOCABSZ);

    loss_rows_kernel<<<NT, 256>>>(out, targets);
    loss_final_kernel<<<1, 256>>>(out, out_size);
}

// round 12
// speedup vs baseline: 2.1504x; 2.1504x over previous
#include <cuda_runtime.h>
#include <cuda_fp16.h>
#include <math.h>
#include <stdint.h>

#define NT    2048      // B*T
#define CDIM  384
#define TDIM  32
#define NHEAD 6
#define HEADD 64
#define VOCABSZ 50257
#define TILE_M 128
#define TILE_N 128
#define NMB   16        // NT/128
#define NNB   393       // ceil(VOCAB/128)
#define NCB   786       // stats blocks of 64 cols (2 per CTA N-tile)
#define KCH   32
#define NCHUNK 12       // 384/32
#define NPAIR  6        // chunk pairs
#define CHUNK_U 2048    // u32 (f16x2) per permuted 128x32 chunk
#define NSTAGE 3
#define STAGE_BYTES 32768   // two chunks: [A0 8K|B0 8K|A1 8K|B1 8K]
#define QKV_MAT_U (3 * NCHUNK * CHUNK_U)

// ---- scratch ----
__device__ float g_h[NT * CDIM];
__device__ float g_q[NT * CDIM];
__device__ float g_k[NT * CDIM];
__device__ float g_v[NT * CDIM];
__device__ float g_pmax[NT * NCB];
__device__ float g_psum[NT * NCB];
__device__ float g_rowloss[NT];
__device__ uint32_t g_aperm[NMB * NCHUNK * CHUNK_U];       // 1.5 MB
__device__ uint32_t g_blm[NNB * NCHUNK * CHUNK_U];         // 38.6 MB
__device__ uint32_t g_bqkv[2 * 3 * QKV_MAT_U];             // 1.7 MB

// =========================================================================
// helpers
// =========================================================================
__device__ __forceinline__ uint32_t smem_u32(const void* p) {
    uint32_t a;
    asm("{ .reg .u64 t; cvta.to.shared.u64 t, %1; cvt.u32.u64 %0, t; }" : "=r"(a) : "l"(p));
    return a;
}
__device__ __forceinline__ uint32_t packh2(float x, float y) {
    __half2 h = __floats2half2_rn(x, y);
    return *(uint32_t*)&h;
}
__device__ __forceinline__ void mma_f16(float c[4], const uint32_t a[4], const uint32_t b[2]) {
    asm volatile(
        "mma.sync.aligned.m16n8k16.row.col.f32.f16.f16.f32 "
        "{%0,%1,%2,%3}, {%4,%5,%6,%7}, {%8,%9}, {%0,%1,%2,%3};"
        : "+f"(c[0]), "+f"(c[1]), "+f"(c[2]), "+f"(c[3])
        : "r"(a[0]), "r"(a[1]), "r"(a[2]), "r"(a[3]), "r"(b[0]), "r"(b[1]));
}
#define LDS128(r, addr) \
    asm volatile("ld.shared.v4.b32 {%0,%1,%2,%3}, [%4];" \
        : "=r"((r)[0]), "=r"((r)[1]), "=r"((r)[2]), "=r"((r)[3]) : "r"(addr))
#define LDS64(r, addr) \
    asm volatile("ld.shared.v2.b32 {%0,%1}, [%2];" \
        : "=r"((r)[0]), "=r"((r)[1]) : "r"(addr))
#define CP_ASYNC16(dst, src) \
    asm volatile("cp.async.cg.shared.global [%0], [%1], 16;" :: "r"(dst), "l"(src) : "memory")
#define CP_COMMIT() asm volatile("cp.async.commit_group;" ::: "memory")
#define CP_WAIT1()  asm volatile("cp.async.wait_group 1;" ::: "memory")

// SMEM: bias[128] @0 ; 3 stages of 32KB @1024 ; epilogue stage (128x132 f32) reuses
#define SM_STAGE0 1024
#define SM_TOTAL  (1024 + NSTAGE * STAGE_BYTES)   // 99328

// fp16 fragment-permuted layouts within a 128x32 chunk (m16n8k16), k0 even:
//  A: s=k0>>4, mb=m>>4, lane=(m&7)*4+((k0>>1)&3), reg=((m>>3)&1)+2*((k0>>3)&1)
//     u32 idx = ((s*8+mb)*32+lane)*4+reg
//  B: s=k0>>4, nb=n>>3, lane=(n&7)*4+((k0>>1)&3), reg=(k0>>3)&1
//     u32 idx = ((s*16+nb)*32+lane)*2+reg

__device__ __forceinline__ void compute_chunk(uint32_t Abuf, uint32_t Bbuf,
                                              int wm, int wn, int lid,
                                              float c[2][8][4]) {
#pragma unroll
    for (int ks = 0; ks < 2; ks++) {
        uint32_t a[2][4];
#pragma unroll
        for (int r = 0; r < 2; r++)
            LDS128(a[r], Abuf + ((ks * 8 + wm * 2 + r) * 32 + lid) * 16);
        uint32_t b[8][2];
#pragma unroll
        for (int nf = 0; nf < 8; nf++)
            LDS64(b[nf], Bbuf + ((ks * 16 + wn * 8 + nf) * 32 + lid) * 8);
#pragma unroll
        for (int r = 0; r < 2; r++)
#pragma unroll
            for (int nf = 0; nf < 8; nf++)
                mma_f16(c[r][nf], a[r], b[nf]);
    }
}

__device__ __forceinline__ void supd(float& m, float& s, float v) {
    if (v > m) { s = s * __expf(m - v) + 1.f; m = v; }
    else       { s += __expf(v - m); }
}

// =========================================================================
// Permutation kernels (global fp32 -> fp16 fragment-permuted global)
// =========================================================================
__global__ void aperm_kernel(const float* __restrict__ A) {
    __shared__ uint32_t sbuf[CHUNK_U];
    const int tid = threadIdx.x;
    const int mb = blockIdx.x, kc = blockIdx.y;
    const int rb = tid >> 3, j = tid & 7;
    const float* Ag = A + (size_t)(mb * 128) * CDIM + kc * KCH + j * 4;
#pragma unroll
    for (int i = 0; i < 4; i++) {
        int r = i * 32 + rb;
        float4 v = *(const float4*)(Ag + (size_t)r * CDIM);
#pragma unroll
        for (int p = 0; p < 2; p++) {
            int k0 = j * 4 + 2 * p;
            int s = k0 >> 4;
            int lane = (r & 7) * 4 + ((k0 >> 1) & 3);
            int reg = ((r >> 3) & 1) + 2 * ((k0 >> 3) & 1);
            int idx = ((s * 8 + (r >> 4)) * 32 + lane) * 4 + reg;
            sbuf[idx] = packh2(p ? v.z : v.x, p ? v.w : v.y);
        }
    }
    __syncthreads();
    uint32_t* out = g_aperm + ((size_t)mb * NCHUNK + kc) * CHUNK_U;
#pragma unroll
    for (int i = 0; i < 2; i++)
        *(uint4*)(out + i * 1024 + tid * 4) = *(const uint4*)&sbuf[i * 1024 + tid * 4];
}

__global__ void bperm_kernel(const float* __restrict__ B0, const float* __restrict__ B1,
                             const float* __restrict__ B2,
                             uint32_t* __restrict__ O0, uint32_t* __restrict__ O1,
                             uint32_t* __restrict__ O2, int Ntot) {
    __shared__ uint32_t sbuf[CHUNK_U];
    const int tid = threadIdx.x;
    const int nb = blockIdx.x, kc = blockIdx.y, z = blockIdx.z;
    const float* B = (z == 0) ? B0 : (z == 1 ? B1 : B2);
    uint32_t* O = (z == 0) ? O0 : (z == 1 ? O1 : O2);
    const int rb = tid >> 3, j = tid & 7;
#pragma unroll
    for (int i = 0; i < 4; i++) {
        int r = i * 32 + rb;
        int n = nb * 128 + r;
        float4 v = (n < Ntot) ? *(const float4*)(B + (size_t)n * CDIM + kc * KCH + j * 4)
                              : make_float4(0.f, 0.f, 0.f, 0.f);
#pragma unroll
        for (int p = 0; p < 2; p++) {
            int k0 = j * 4 + 2 * p;
            int s = k0 >> 4;
            int lane = (r & 7) * 4 + ((k0 >> 1) & 3);
            int reg = (k0 >> 3) & 1;
            int idx = ((s * 16 + (r >> 3)) * 32 + lane) * 2 + reg;
            sbuf[idx] = packh2(p ? v.z : v.x, p ? v.w : v.y);
        }
    }
    __syncthreads();
    uint32_t* out = O + ((size_t)nb * NCHUNK + kc) * CHUNK_U;
#pragma unroll
    for (int i = 0; i < 2; i++)
        *(uint4*)(out + i * 1024 + tid * 4) = *(const uint4*)&sbuf[i * 1024 + tid * 4];
}

// =========================================================================
// fp16 tensor GEMM over pre-permuted operands. 128x128 tile, 256 threads.
// K processed in pairs of 32-chunks (64 per stage).
// grid: (NMB, Nblocks, nz); z selects B/C pair (fused QKV). A = g_aperm.
// =========================================================================
template <bool STATS>
__global__ __launch_bounds__(256)
void mma_gemm(const uint32_t* __restrict__ Bp0, const uint32_t* __restrict__ Bp1,
              const uint32_t* __restrict__ Bp2,
              float* __restrict__ C0, float* __restrict__ C1, float* __restrict__ C2,
              const float* __restrict__ bias, int Ntot) {
    extern __shared__ __align__(1024) char smem[];
    const int tid = threadIdx.x;
    const int lid = tid & 31, wid = tid >> 5;
    const int wm = wid >> 1, wn = wid & 1;
    const int bm = blockIdx.x * TILE_M;
    const int bn = blockIdx.y * TILE_N;
    const uint32_t* Bperm = (blockIdx.z == 0) ? Bp0 : (blockIdx.z == 1 ? Bp1 : Bp2);
    float* C = (blockIdx.z == 0) ? C0 : (blockIdx.z == 1 ? C1 : C2);

    const uint32_t* Ac = g_aperm + (size_t)blockIdx.x * NCHUNK * CHUNK_U;
    const uint32_t* Bc = Bperm + (size_t)blockIdx.y * NCHUNK * CHUNK_U;

    float* biasS = (float*)smem;
    float* stage = (float*)(smem + SM_STAGE0);
    const uint32_t sb = smem_u32(smem);

    if (tid < TILE_N) {
        int n = bn + tid;
        biasS[tid] = (bias != nullptr && n < Ntot) ? bias[n] : 0.f;
    }

    float c[2][8][4];
#pragma unroll
    for (int r = 0; r < 2; r++)
#pragma unroll
        for (int nf = 0; nf < 8; nf++)
#pragma unroll
            for (int e = 0; e < 4; e++) c[r][nf][e] = 0.f;

    // ---- cp.async: copy chunk pair (2*kp, 2*kp+1) into stage s ----
    // stage layout: [A0 8K | B0 8K | A1 8K | B1 8K]
    auto issue_pair = [&](int kp, int s) {
        uint32_t base = sb + SM_STAGE0 + s * STAGE_BYTES + tid * 16;
#pragma unroll
        for (int u = 0; u < 2; u++) {
            const uint32_t* srcA = Ac + (size_t)(2 * kp + u) * CHUNK_U + tid * 4;
            const uint32_t* srcB = Bc + (size_t)(2 * kp + u) * CHUNK_U + tid * 4;
            CP_ASYNC16(base + u * 16384, srcA);
            CP_ASYNC16(base + u * 16384 + 4096, srcA + 1024);
            CP_ASYNC16(base + u * 16384 + 8192, srcB);
            CP_ASYNC16(base + u * 16384 + 12288, srcB + 1024);
        }
    };

    issue_pair(0, 0); CP_COMMIT();
    issue_pair(1, 1); CP_COMMIT();

    for (int kp = 0; kp < NPAIR; kp++) {
        CP_WAIT1();
        __syncthreads();                 // pair kp visible; stage (kp+2)%3 free
        if (kp + 2 < NPAIR) issue_pair(kp + 2, (kp + 2) % NSTAGE);
        CP_COMMIT();
        const uint32_t base = sb + SM_STAGE0 + (kp % NSTAGE) * STAGE_BYTES;
        compute_chunk(base, base + 8192, wm, wn, lid, c);
        compute_chunk(base + 16384, base + 24576, wm, wn, lid, c);
    }
    __syncthreads();                     // compute done before stage reuse

    // ---- epilogue ----
    const int g = lid >> 2, t4 = lid & 3;
    const bool full = (bn + TILE_N <= Ntot);

    // fold bias into accumulators
#pragma unroll
    for (int r = 0; r < 2; r++)
#pragma unroll
        for (int nf = 0; nf < 8; nf++) {
            const int col = wn * 64 + nf * 8 + t4 * 2;
            const float b0 = biasS[col], b1 = biasS[col + 1];
            c[r][nf][0] += b0; c[r][nf][1] += b1;
            c[r][nf][2] += b0; c[r][nf][3] += b1;
        }

    if (STATS) {
        float rm[2][2], rs[2][2];
#pragma unroll
        for (int r = 0; r < 2; r++)
#pragma unroll
            for (int h = 0; h < 2; h++) { rm[r][h] = -INFINITY; rs[r][h] = 0.f; }
        if (full) {
            // branch-free: tree max, then independent exps
#pragma unroll
            for (int r = 0; r < 2; r++)
#pragma unroll
                for (int nf = 0; nf < 8; nf++) {
                    rm[r][0] = fmaxf(rm[r][0], fmaxf(c[r][nf][0], c[r][nf][1]));
                    rm[r][1] = fmaxf(rm[r][1], fmaxf(c[r][nf][2], c[r][nf][3]));
                }
#pragma unroll
            for (int r = 0; r < 2; r++)
#pragma unroll
                for (int nf = 0; nf < 8; nf++) {
                    rs[r][0] += __expf(c[r][nf][0] - rm[r][0]) +
                                __expf(c[r][nf][1] - rm[r][0]);
                    rs[r][1] += __expf(c[r][nf][2] - rm[r][1]) +
                                __expf(c[r][nf][3] - rm[r][1]);
                }
        } else {
#pragma unroll
            for (int r = 0; r < 2; r++)
#pragma unroll
                for (int nf = 0; nf < 8; nf++) {
                    const int n = bn + wn * 64 + nf * 8 + t4 * 2;
                    if (n < Ntot)     { supd(rm[r][0], rs[r][0], c[r][nf][0]);
                                        supd(rm[r][1], rs[r][1], c[r][nf][2]); }
                    if (n + 1 < Ntot) { supd(rm[r][0], rs[r][0], c[r][nf][1]);
                                        supd(rm[r][1], rs[r][1], c[r][nf][3]); }
                }
        }
#pragma unroll
        for (int r = 0; r < 2; r++)
#pragma unroll
            for (int h = 0; h < 2; h++) {
                float m = rm[r][h], s = rs[r][h];
#pragma unroll
                for (int off = 1; off <= 2; off <<= 1) {
                    float om = __shfl_xor_sync(0xffffffffu, m, off);
                    float os = __shfl_xor_sync(0xffffffffu, s, off);
                    float M = fmaxf(m, om);
                    float S = ((m > -INFINITY) ? s * __expf(m - M) : 0.f) +
                              ((om > -INFINITY) ? os * __expf(om - M) : 0.f);
                    m = M; s = S;
                }
                if (t4 == 0) {
                    int mrow = bm + wm * 32 + r * 16 + h * 8 + g;
                    size_t idx = (size_t)mrow * NCB + blockIdx.y * 2 + wn;
                    g_pmax[idx] = m;
                    g_psum[idx] = s;
                }
            }
    }

    // staged coalesced store
#pragma unroll
    for (int r = 0; r < 2; r++) {
        const int row = wm * 32 + r * 16 + g;
#pragma unroll
        for (int nf = 0; nf < 8; nf++) {
            const int col = wn * 64 + nf * 8 + t4 * 2;
            *(float2*)&stage[row * 132 + col] = make_float2(c[r][nf][0], c[r][nf][1]);
            *(float2*)&stage[(row + 8) * 132 + col] = make_float2(c[r][nf][2], c[r][nf][3]);
        }
    }
    __syncthreads();
    if (full) {
#pragma unroll 8
        for (int it = 0; it < 64; it++) {
            int idx = it * 256 + tid;
            int rr = idx >> 7, cc = idx & 127;
            C[(size_t)(bm + rr) * Ntot + bn + cc] = stage[rr * 132 + cc];
        }
    } else {
#pragma unroll 8
        for (int it = 0; it < 64; it++) {
            int idx = it * 256 + tid;
            int rr = idx >> 7, cc = idx & 127;
            int n = bn + cc;
            if (n < Ntot) C[(size_t)(bm + rr) * Ntot + n] = stage[rr * 132 + cc];
        }
    }
}

// =========================================================================
// Embedding
// =========================================================================
__global__ void embed_kernel(const int* __restrict__ x,
                             const float* __restrict__ w_e,
                             const float* __restrict__ pos) {
    int idx = blockIdx.x * blockDim.x + threadIdx.x;
    if (idx >= NT * CDIM) return;
    int bt = idx / CDIM, c = idx % CDIM;
    int tok = x[bt];
    g_h[idx] = w_e[(size_t)tok * CDIM + c] + pos[(bt % TDIM) * CDIM + c];
}

// =========================================================================
// Attention (T=32, D=64, causal, h += attn)
// =========================================================================
__global__ void attn_kernel() {
    __shared__ float qs[32][65];
    __shared__ float ks[32][65];
    __shared__ float vs[32][65];
    __shared__ float w[32][33];

    const int bh = blockIdx.x;
    const int b = bh / NHEAD, hd = bh % NHEAD;
    const int tid = threadIdx.x;
    const int base = (b * TDIM) * CDIM + hd * HEADD;

    for (int i = tid; i < 32 * 64; i += 256) {
        int t = i >> 6, d = i & 63;
        int g = base + t * CDIM + d;
        qs[t][d] = g_q[g];
        ks[t][d] = g_k[g];
        vs[t][d] = g_v[g];
    }
    __syncthreads();

    const float scale = 0.125f;
    for (int i = tid; i < 32 * 32; i += 256) {
        int t = i >> 5, s = i & 31;
        float v = -INFINITY;
        if (s <= t) {
            float acc = 0.f;
#pragma unroll
            for (int d = 0; d < 64; d++) acc += qs[t][d] * ks[s][d];
            v = acc * scale;
        }
        w[t][s] = v;
    }
    __syncthreads();

    if (tid < 32) {
        int t = tid;
        float mx = -INFINITY;
        for (int s = 0; s <= t; s++) mx = fmaxf(mx, w[t][s]);
        float sum = 0.f;
        for (int s = 0; s <= t; s++) { float e = expf(w[t][s] - mx); w[t][s] = e; sum += e; }
        float inv = 1.f / sum;
        for (int s = 0; s <= t; s++) w[t][s] *= inv;
        for (int s = t + 1; s < 32; s++) w[t][s] = 0.f;
    }
    __syncthreads();

    for (int i = tid; i < 32 * 64; i += 256) {
        int t = i >> 6, d = i & 63;
        float acc = 0.f;
#pragma unroll
        for (int s = 0; s < 32; s++) acc += w[t][s] * vs[s][d];
        g_h[base + t * CDIM + d] += acc;
    }
}

// =========================================================================
// Loss
// =========================================================================
__global__ void loss_rows_kernel(const float* __restrict__ logits,
                                 const int* __restrict__ targets) {
    const int row = blockIdx.x;
    const int tid = threadIdx.x;
    float m = -INFINITY, s = 0.f;
    for (int cb = tid; cb < NCB; cb += 256) {
        float mi = g_pmax[(size_t)row * NCB + cb];
        float si = g_psum[(size_t)row * NCB + cb];
        if (mi > m) { s = s * expf(m - mi) + si; m = mi; }
        else if (mi > -INFINITY) { s += si * expf(mi - m); }
    }
    __shared__ float sm[256], ss[256];
    sm[tid] = m; ss[tid] = s;
    __syncthreads();
    for (int st = 128; st > 0; st >>= 1) {
        if (tid < st) {
            float m1 = sm[tid], s1 = ss[tid];
            float m2 = sm[tid + st], s2 = ss[tid + st];
            float M = fmaxf(m1, m2);
            float S = ((m1 > -INFINITY) ? s1 * expf(m1 - M) : 0.f) +
                      ((m2 > -INFINITY) ? s2 * expf(m2 - M) : 0.f);
            sm[tid] = M; ss[tid] = S;
        }
        __syncthreads();
    }
    if (tid == 0) {
        float logZ = sm[0] + logf(ss[0]);
        int t = targets[row];
        float lt = logits[(size_t)row * VOCABSZ + t];
        g_rowloss[row] = logZ - lt;
    }
}

__global__ void loss_final_kernel(float* __restrict__ out, int out_size) {
    __shared__ float sm[256];
    const int tid = threadIdx.x;
    float s = 0.f;
    for (int r = tid; r < NT; r += 256) s += g_rowloss[r];
    sm[tid] = s;
    __syncthreads();
    for (int st = 128; st > 0; st >>= 1) {
        if (tid < st) sm[tid] += sm[tid + st];
        __syncthreads();
    }
    if (tid == 0) {
        float loss = sm[0] / (float)NT;
        size_t logits_elems = (size_t)NT * VOCABSZ;
        if ((size_t)out_size > logits_elems) out[logits_elems] = loss;
    }
}

// =========================================================================
extern "C" void kernel_launch(void* const* d_in, const int* in_sizes, int n_in,
                              void* d_out, int out_size) {
    const int*   x       = (const int*)d_in[0];
    const int*   targets = (const int*)d_in[1];
    const float* w_e     = (const float*)d_in[2];
    const float* pos     = (const float*)d_in[3];
    const float* Wq      = (const float*)d_in[4];
    const float* Wk      = (const float*)d_in[5];
    const float* Wv      = (const float*)d_in[6];
    const float* lm_w    = (const float*)d_in[7];
    const float* lm_b    = (const float*)d_in[8];
    float* out = (float*)d_out;

    float *ph, *pq, *pk, *pv;
    uint32_t *pblm, *pbqkv;
    cudaGetSymbolAddress((void**)&ph, g_h);
    cudaGetSymbolAddress((void**)&pq, g_q);
    cudaGetSymbolAddress((void**)&pk, g_k);
    cudaGetSymbolAddress((void**)&pv, g_v);
    cudaGetSymbolAddress((void**)&pblm, g_blm);
    cudaGetSymbolAddress((void**)&pbqkv, g_bqkv);

    cudaFuncSetAttribute(mma_gemm<false>, cudaFuncAttributeMaxDynamicSharedMemorySize, SM_TOTAL);
    cudaFuncSetAttribute(mma_gemm<true>,  cudaFuncAttributeMaxDynamicSharedMemorySize, SM_TOTAL);

    embed_kernel<<<(NT * CDIM + 255) / 256, 256>>>(x, w_e, pos);

    const size_t wstride = (size_t)NHEAD * HEADD * CDIM;
    // permute all weights (lm_w + 2 layers of Q/K/V)
    bperm_kernel<<<dim3(NNB, NCHUNK, 1), 256>>>(lm_w, lm_w, lm_w, pblm, pblm, pblm, VOCABSZ);
    for (int l = 0; l < 2; l++) {
        uint32_t* bq = pbqkv + (size_t)(l * 3 + 0) * QKV_MAT_U;
        uint32_t* bk = pbqkv + (size_t)(l * 3 + 1) * QKV_MAT_U;
        uint32_t* bv = pbqkv + (size_t)(l * 3 + 2) * QKV_MAT_U;
        bperm_kernel<<<dim3(3, NCHUNK, 3), 256>>>(
            Wq + l * wstride, Wk + l * wstride, Wv + l * wstride, bq, bk, bv, CDIM);
    }

    for (int l = 0; l < 2; l++) {
        uint32_t* bq = pbqkv + (size_t)(l * 3 + 0) * QKV_MAT_U;
        uint32_t* bk = pbqkv + (size_t)(l * 3 + 1) * QKV_MAT_U;
        uint32_t* bv = pbqkv + (size_t)(l * 3 + 2) * QKV_MAT_U;
        aperm_kernel<<<dim3(NMB, NCHUNK), 256>>>(ph);
        mma_gemm<false><<<dim3(NMB, 3, 3), 256, SM_TOTAL>>>(
            bq, bk, bv, pq, pk, pv, nullptr, CDIM);
        attn_kernel<<<(NT / TDIM) * NHEAD, 256>>>();
    }

    aperm_kernel<<<dim3(NMB, NCHUNK), 256>>>(ph);
    mma_gemm<true><<<dim3(NMB, NNB, 1), 256, SM_TOTAL>>>(
        pblm, pblm, pblm, out, out, out, lm_b, VOCABSZ);

    loss_rows_kernel<<<NT, 256>>>(out, targets);
    loss_final_kernel<<<1, 256>>>(out, out_size);
}

// round 13
// speedup vs baseline: 2.1943x; 1.0204x over previous
#include <cuda_runtime.h>
#include <cuda_fp16.h>
#include <math.h>
#include <stdint.h>

#define NT    2048      // B*T
#define CDIM  384
#define TDIM  32
#define NHEAD 6
#define HEADD 64
#define VOCABSZ 50257
#define TILE_M 128
#define TILE_N 128
#define NMB   16        // NT/128
#define NNB   393       // ceil(VOCAB/128)
#define NCB   786       // stats blocks of 64 cols (2 per CTA N-tile)
#define KCH   32
#define NCHUNK 12       // 384/32
#define NPAIR  6        // chunk pairs
#define CHUNK_U 2048    // u32 (f16x2) per permuted 128x32 chunk
#define NSTAGE 3
#define STAGE_BYTES 32768   // two chunks: [A0 8K|B0 8K|A1 8K|B1 8K]
#define QKV_MAT_U (3 * NCHUNK * CHUNK_U)

// ---- scratch ----
__device__ float g_h[NT * CDIM];
__device__ float g_q[NT * CDIM];
__device__ float g_k[NT * CDIM];
__device__ float g_v[NT * CDIM];
__device__ float g_pmax[NT * NCB];
__device__ float g_psum[NT * NCB];
__device__ float g_rowloss[NT];
__device__ uint32_t g_aperm[NMB * NCHUNK * CHUNK_U];       // 1.5 MB
__device__ uint32_t g_blm[NNB * NCHUNK * CHUNK_U];         // 38.6 MB
__device__ uint32_t g_bqkv[2 * 3 * QKV_MAT_U];             // 1.7 MB

// =========================================================================
// helpers
// =========================================================================
__device__ __forceinline__ uint32_t smem_u32(const void* p) {
    uint32_t a;
    asm("{ .reg .u64 t; cvta.to.shared.u64 t, %1; cvt.u32.u64 %0, t; }" : "=r"(a) : "l"(p));
    return a;
}
__device__ __forceinline__ uint32_t packh2(float x, float y) {
    __half2 h = __floats2half2_rn(x, y);
    return *(uint32_t*)&h;
}
__device__ __forceinline__ void mma_f16(float c[4], const uint32_t a[4], const uint32_t b[2]) {
    asm volatile(
        "mma.sync.aligned.m16n8k16.row.col.f32.f16.f16.f32 "
        "{%0,%1,%2,%3}, {%4,%5,%6,%7}, {%8,%9}, {%0,%1,%2,%3};"
        : "+f"(c[0]), "+f"(c[1]), "+f"(c[2]), "+f"(c[3])
        : "r"(a[0]), "r"(a[1]), "r"(a[2]), "r"(a[3]), "r"(b[0]), "r"(b[1]));
}
#define LDS128(r, addr) \
    asm volatile("ld.shared.v4.b32 {%0,%1,%2,%3}, [%4];" \
        : "=r"((r)[0]), "=r"((r)[1]), "=r"((r)[2]), "=r"((r)[3]) : "r"(addr))
#define LDS64(r, addr) \
    asm volatile("ld.shared.v2.b32 {%0,%1}, [%2];" \
        : "=r"((r)[0]), "=r"((r)[1]) : "r"(addr))
#define CP_ASYNC16(dst, src) \
    asm volatile("cp.async.cg.shared.global [%0], [%1], 16;" :: "r"(dst), "l"(src) : "memory")
#define CP_COMMIT() asm volatile("cp.async.commit_group;" ::: "memory")
#define CP_WAIT1()  asm volatile("cp.async.wait_group 1;" ::: "memory")

// SMEM: bias[128] @0 ; 3 stages of 32KB @1024 ; epilogue stage (128x132 f32) reuses
#define SM_STAGE0 1024
#define SM_TOTAL  (1024 + NSTAGE * STAGE_BYTES)   // 99328

// fp16 fragment-permuted layouts within a 128x32 chunk (m16n8k16), k0 even:
//  A: s=k0>>4, mb=m>>4, lane=(m&7)*4+((k0>>1)&3), reg=((m>>3)&1)+2*((k0>>3)&1)
//     u32 idx = ((s*8+mb)*32+lane)*4+reg
//  B: s=k0>>4, nb=n>>3, lane=(n&7)*4+((k0>>1)&3), reg=(k0>>3)&1
//     u32 idx = ((s*16+nb)*32+lane)*2+reg
__device__ __forceinline__ int aperm_idx(int r, int k0c) {
    // r = row within 128, k0c = even k within 32
    return (((k0c >> 4) * 8 + (r >> 4)) * 32 + (r & 7) * 4 + ((k0c >> 1) & 3)) * 4
           + ((r >> 3) & 1) + 2 * ((k0c >> 3) & 1);
}

__device__ __forceinline__ void compute_chunk(uint32_t Abuf, uint32_t Bbuf,
                                              int wm, int wn, int lid,
                                              float c[2][8][4]) {
#pragma unroll
    for (int ks = 0; ks < 2; ks++) {
        uint32_t a[2][4];
#pragma unroll
        for (int r = 0; r < 2; r++)
            LDS128(a[r], Abuf + ((ks * 8 + wm * 2 + r) * 32 + lid) * 16);
        uint32_t b[8][2];
#pragma unroll
        for (int nf = 0; nf < 8; nf++)
            LDS64(b[nf], Bbuf + ((ks * 16 + wn * 8 + nf) * 32 + lid) * 8);
#pragma unroll
        for (int r = 0; r < 2; r++)
#pragma unroll
            for (int nf = 0; nf < 8; nf++)
                mma_f16(c[r][nf], a[r], b[nf]);
    }
}

__device__ __forceinline__ void supd(float& m, float& s, float v) {
    if (v > m) { s = s * __expf(m - v) + 1.f; m = v; }
    else       { s += __expf(v - m); }
}

// =========================================================================
// Fused embedding + A-permutation: h = w_e[x] + pos; also emit fp16 perm chunk
// grid (NMB, NCHUNK), 256 threads
// =========================================================================
__global__ void embed_perm_kernel(const int* __restrict__ x,
                                  const float* __restrict__ w_e,
                                  const float* __restrict__ pos) {
    __shared__ uint32_t sbuf[CHUNK_U];
    const int tid = threadIdx.x;
    const int mb = blockIdx.x, kc = blockIdx.y;
    const int rb = tid >> 3, j = tid & 7;
#pragma unroll
    for (int i = 0; i < 4; i++) {
        int r = i * 32 + rb;
        int m = mb * 128 + r;
        int tok = x[m];
        const float* we = w_e + (size_t)tok * CDIM + kc * KCH + j * 4;
        const float* pp = pos + (size_t)(m & (TDIM - 1)) * CDIM + kc * KCH + j * 4;
        float4 v;
        v.x = we[0] + pp[0]; v.y = we[1] + pp[1];
        v.z = we[2] + pp[2]; v.w = we[3] + pp[3];
        *(float4*)&g_h[(size_t)m * CDIM + kc * KCH + j * 4] = v;
#pragma unroll
        for (int p = 0; p < 2; p++) {
            int k0 = j * 4 + 2 * p;
            sbuf[aperm_idx(r, k0)] = packh2(p ? v.z : v.x, p ? v.w : v.y);
        }
    }
    __syncthreads();
    uint32_t* out = g_aperm + ((size_t)mb * NCHUNK + kc) * CHUNK_U;
#pragma unroll
    for (int i = 0; i < 2; i++)
        *(uint4*)(out + i * 1024 + tid * 4) = *(const uint4*)&sbuf[i * 1024 + tid * 4];
}

// =========================================================================
// B-permutation kernels (global fp32 -> fp16 fragment-permuted global)
// =========================================================================
__global__ void bperm_kernel(const float* __restrict__ B,
                             uint32_t* __restrict__ O, int Ntot) {
    __shared__ uint32_t sbuf[CHUNK_U];
    const int tid = threadIdx.x;
    const int nb = blockIdx.x, kc = blockIdx.y;
    const int rb = tid >> 3, j = tid & 7;
#pragma unroll
    for (int i = 0; i < 4; i++) {
        int r = i * 32 + rb;
        int n = nb * 128 + r;
        float4 v = (n < Ntot) ? *(const float4*)(B + (size_t)n * CDIM + kc * KCH + j * 4)
                              : make_float4(0.f, 0.f, 0.f, 0.f);
#pragma unroll
        for (int p = 0; p < 2; p++) {
            int k0 = j * 4 + 2 * p;
            int idx = (((k0 >> 4) * 16 + (r >> 3)) * 32 + (r & 7) * 4 + ((k0 >> 1) & 3)) * 2
                      + ((k0 >> 3) & 1);
            sbuf[idx] = packh2(p ? v.z : v.x, p ? v.w : v.y);
        }
    }
    __syncthreads();
    uint32_t* out = O + ((size_t)nb * NCHUNK + kc) * CHUNK_U;
#pragma unroll
    for (int i = 0; i < 2; i++)
        *(uint4*)(out + i * 1024 + tid * 4) = *(const uint4*)&sbuf[i * 1024 + tid * 4];
}

// all 6 QKV weight matrices in one launch: grid (3, NCHUNK, 6), z = l*3+mat
__global__ void bperm_qkv_kernel(const float* __restrict__ Wq,
                                 const float* __restrict__ Wk,
                                 const float* __restrict__ Wv,
                                 uint32_t* __restrict__ Oall) {
    __shared__ uint32_t sbuf[CHUNK_U];
    const int tid = threadIdx.x;
    const int nb = blockIdx.x, kc = blockIdx.y, z = blockIdx.z;
    const int l = z / 3, mat = z % 3;
    const size_t wstride = (size_t)NHEAD * HEADD * CDIM;
    const float* B = ((mat == 0) ? Wq : (mat == 1) ? Wk : Wv) + l * wstride;
    uint32_t* O = Oall + (size_t)z * QKV_MAT_U;
    const int rb = tid >> 3, j = tid & 7;
#pragma unroll
    for (int i = 0; i < 4; i++) {
        int r = i * 32 + rb;
        float4 v = *(const float4*)(B + (size_t)(nb * 128 + r) * CDIM + kc * KCH + j * 4);
#pragma unroll
        for (int p = 0; p < 2; p++) {
            int k0 = j * 4 + 2 * p;
            int idx = (((k0 >> 4) * 16 + (r >> 3)) * 32 + (r & 7) * 4 + ((k0 >> 1) & 3)) * 2
                      + ((k0 >> 3) & 1);
            sbuf[idx] = packh2(p ? v.z : v.x, p ? v.w : v.y);
        }
    }
    __syncthreads();
    uint32_t* out = O + ((size_t)nb * NCHUNK + kc) * CHUNK_U;
#pragma unroll
    for (int i = 0; i < 2; i++)
        *(uint4*)(out + i * 1024 + tid * 4) = *(const uint4*)&sbuf[i * 1024 + tid * 4];
}

// =========================================================================
// fp16 tensor GEMM over pre-permuted operands. 128x128 tile, 256 threads.
// (unchanged from R12 — at HMMA issue floor)
// =========================================================================
template <bool STATS>
__global__ __launch_bounds__(256)
void mma_gemm(const uint32_t* __restrict__ Bp0, const uint32_t* __restrict__ Bp1,
              const uint32_t* __restrict__ Bp2,
              float* __restrict__ C0, float* __restrict__ C1, float* __restrict__ C2,
              const float* __restrict__ bias, int Ntot) {
    extern __shared__ __align__(1024) char smem[];
    const int tid = threadIdx.x;
    const int lid = tid & 31, wid = tid >> 5;
    const int wm = wid >> 1, wn = wid & 1;
    const int bm = blockIdx.x * TILE_M;
    const int bn = blockIdx.y * TILE_N;
    const uint32_t* Bperm = (blockIdx.z == 0) ? Bp0 : (blockIdx.z == 1 ? Bp1 : Bp2);
    float* C = (blockIdx.z == 0) ? C0 : (blockIdx.z == 1 ? C1 : C2);

    const uint32_t* Ac = g_aperm + (size_t)blockIdx.x * NCHUNK * CHUNK_U;
    const uint32_t* Bc = Bperm + (size_t)blockIdx.y * NCHUNK * CHUNK_U;

    float* biasS = (float*)smem;
    float* stage = (float*)(smem + SM_STAGE0);
    const uint32_t sb = smem_u32(smem);

    if (tid < TILE_N) {
        int n = bn + tid;
        biasS[tid] = (bias != nullptr && n < Ntot) ? bias[n] : 0.f;
    }

    float c[2][8][4];
#pragma unroll
    for (int r = 0; r < 2; r++)
#pragma unroll
        for (int nf = 0; nf < 8; nf++)
#pragma unroll
            for (int e = 0; e < 4; e++) c[r][nf][e] = 0.f;

    auto issue_pair = [&](int kp, int s) {
        uint32_t base = sb + SM_STAGE0 + s * STAGE_BYTES + tid * 16;
#pragma unroll
        for (int u = 0; u < 2; u++) {
            const uint32_t* srcA = Ac + (size_t)(2 * kp + u) * CHUNK_U + tid * 4;
            const uint32_t* srcB = Bc + (size_t)(2 * kp + u) * CHUNK_U + tid * 4;
            CP_ASYNC16(base + u * 16384, srcA);
            CP_ASYNC16(base + u * 16384 + 4096, srcA + 1024);
            CP_ASYNC16(base + u * 16384 + 8192, srcB);
            CP_ASYNC16(base + u * 16384 + 12288, srcB + 1024);
        }
    };

    issue_pair(0, 0); CP_COMMIT();
    issue_pair(1, 1); CP_COMMIT();

    for (int kp = 0; kp < NPAIR; kp++) {
        CP_WAIT1();
        __syncthreads();
        if (kp + 2 < NPAIR) issue_pair(kp + 2, (kp + 2) % NSTAGE);
        CP_COMMIT();
        const uint32_t base = sb + SM_STAGE0 + (kp % NSTAGE) * STAGE_BYTES;
        compute_chunk(base, base + 8192, wm, wn, lid, c);
        compute_chunk(base + 16384, base + 24576, wm, wn, lid, c);
    }
    __syncthreads();

    const int g = lid >> 2, t4 = lid & 3;
    const bool full = (bn + TILE_N <= Ntot);

#pragma unroll
    for (int r = 0; r < 2; r++)
#pragma unroll
        for (int nf = 0; nf < 8; nf++) {
            const int col = wn * 64 + nf * 8 + t4 * 2;
            const float b0 = biasS[col], b1 = biasS[col + 1];
            c[r][nf][0] += b0; c[r][nf][1] += b1;
            c[r][nf][2] += b0; c[r][nf][3] += b1;
        }

    if (STATS) {
        float rm[2][2], rs[2][2];
#pragma unroll
        for (int r = 0; r < 2; r++)
#pragma unroll
            for (int h = 0; h < 2; h++) { rm[r][h] = -INFINITY; rs[r][h] = 0.f; }
        if (full) {
#pragma unroll
            for (int r = 0; r < 2; r++)
#pragma unroll
                for (int nf = 0; nf < 8; nf++) {
                    rm[r][0] = fmaxf(rm[r][0], fmaxf(c[r][nf][0], c[r][nf][1]));
                    rm[r][1] = fmaxf(rm[r][1], fmaxf(c[r][nf][2], c[r][nf][3]));
                }
#pragma unroll
            for (int r = 0; r < 2; r++)
#pragma unroll
                for (int nf = 0; nf < 8; nf++) {
                    rs[r][0] += __expf(c[r][nf][0] - rm[r][0]) +
                                __expf(c[r][nf][1] - rm[r][0]);
                    rs[r][1] += __expf(c[r][nf][2] - rm[r][1]) +
                                __expf(c[r][nf][3] - rm[r][1]);
                }
        } else {
#pragma unroll
            for (int r = 0; r < 2; r++)
#pragma unroll
                for (int nf = 0; nf < 8; nf++) {
                    const int n = bn + wn * 64 + nf * 8 + t4 * 2;
                    if (n < Ntot)     { supd(rm[r][0], rs[r][0], c[r][nf][0]);
                                        supd(rm[r][1], rs[r][1], c[r][nf][2]); }
                    if (n + 1 < Ntot) { supd(rm[r][0], rs[r][0], c[r][nf][1]);
                                        supd(rm[r][1], rs[r][1], c[r][nf][3]); }
                }
        }
#pragma unroll
        for (int r = 0; r < 2; r++)
#pragma unroll
            for (int h = 0; h < 2; h++) {
                float m = rm[r][h], s = rs[r][h];
#pragma unroll
                for (int off = 1; off <= 2; off <<= 1) {
                    float om = __shfl_xor_sync(0xffffffffu, m, off);
                    float os = __shfl_xor_sync(0xffffffffu, s, off);
                    float M = fmaxf(m, om);
                    float S = ((m > -INFINITY) ? s * __expf(m - M) : 0.f) +
                              ((om > -INFINITY) ? os * __expf(om - M) : 0.f);
                    m = M; s = S;
                }
                if (t4 == 0) {
                    int mrow = bm + wm * 32 + r * 16 + h * 8 + g;
                    size_t idx = (size_t)mrow * NCB + blockIdx.y * 2 + wn;
                    g_pmax[idx] = m;
                    g_psum[idx] = s;
                }
            }
    }

#pragma unroll
    for (int r = 0; r < 2; r++) {
        const int row = wm * 32 + r * 16 + g;
#pragma unroll
        for (int nf = 0; nf < 8; nf++) {
            const int col = wn * 64 + nf * 8 + t4 * 2;
            *(float2*)&stage[row * 132 + col] = make_float2(c[r][nf][0], c[r][nf][1]);
            *(float2*)&stage[(row + 8) * 132 + col] = make_float2(c[r][nf][2], c[r][nf][3]);
        }
    }
    __syncthreads();
    if (full) {
#pragma unroll 8
        for (int it = 0; it < 64; it++) {
            int idx = it * 256 + tid;
            int rr = idx >> 7, cc = idx & 127;
            C[(size_t)(bm + rr) * Ntot + bn + cc] = stage[rr * 132 + cc];
        }
    } else {
#pragma unroll 8
        for (int it = 0; it < 64; it++) {
            int idx = it * 256 + tid;
            int rr = idx >> 7, cc = idx & 127;
            int n = bn + cc;
            if (n < Ntot) C[(size_t)(bm + rr) * Ntot + n] = stage[rr * 132 + cc];
        }
    }
}

// =========================================================================
// Attention (T=32, D=64, causal) — updates g_h AND writes permuted fp16 chunks
// =========================================================================
__global__ void attn_kernel() {
    __shared__ float qs[32][65];
    __shared__ float ks[32][65];
    __shared__ float vs[32][65];
    __shared__ float w[32][33];

    const int bh = blockIdx.x;
    const int b = bh / NHEAD, hd = bh % NHEAD;
    const int tid = threadIdx.x;
    const int base = (b * TDIM) * CDIM + hd * HEADD;

    for (int i = tid; i < 32 * 64; i += 256) {
        int t = i >> 6, d = i & 63;
        int g = base + t * CDIM + d;
        qs[t][d] = g_q[g];
        ks[t][d] = g_k[g];
        vs[t][d] = g_v[g];
    }
    __syncthreads();

    const float scale = 0.125f;
    for (int i = tid; i < 32 * 32; i += 256) {
        int t = i >> 5, s = i & 31;
        float v = -INFINITY;
        if (s <= t) {
            float acc = 0.f;
#pragma unroll
            for (int d = 0; d < 64; d++) acc += qs[t][d] * ks[s][d];
            v = acc * scale;
        }
        w[t][s] = v;
    }
    __syncthreads();

    if (tid < 32) {
        int t = tid;
        float mx = -INFINITY;
        for (int s = 0; s <= t; s++) mx = fmaxf(mx, w[t][s]);
        float sum = 0.f;
        for (int s = 0; s <= t; s++) { float e = expf(w[t][s] - mx); w[t][s] = e; sum += e; }
        float inv = 1.f / sum;
        for (int s = 0; s <= t; s++) w[t][s] *= inv;
        for (int s = t + 1; s < 32; s++) w[t][s] = 0.f;
    }
    __syncthreads();

    // h update + permuted fp16 emission (two adjacent d per thread)
    for (int i = tid; i < 32 * 32; i += 256) {
        int t = i >> 5, d0 = (i & 31) * 2;
        float a0 = 0.f, a1 = 0.f;
#pragma unroll
        for (int s = 0; s < 32; s++) {
            a0 += w[t][s] * vs[s][d0];
            a1 += w[t][s] * vs[s][d0 + 1];
        }
        const int off = base + t * CDIM + d0;
        float2 hv = *(float2*)&g_h[off];
        hv.x += a0; hv.y += a1;
        *(float2*)&g_h[off] = hv;
        // permuted write
        const int m = b * TDIM + t;
        const int k0 = hd * HEADD + d0;
        const int kc = k0 >> 5, k0c = k0 & 31;
        g_aperm[((size_t)(m >> 7) * NCHUNK + kc) * CHUNK_U + aperm_idx(m & 127, k0c)] =
            packh2(hv.x, hv.y);
    }
}

// =========================================================================
// Loss
// =========================================================================
__global__ void loss_rows_kernel(const float* __restrict__ logits,
                                 const int* __restrict__ targets) {
    const int row = blockIdx.x;
    const int tid = threadIdx.x;
    float m = -INFINITY, s = 0.f;
    for (int cb = tid; cb < NCB; cb += 256) {
        float mi = g_pmax[(size_t)row * NCB + cb];
        float si = g_psum[(size_t)row * NCB + cb];
        if (mi > m) { s = s * expf(m - mi) + si; m = mi; }
        else if (mi > -INFINITY) { s += si * expf(mi - m); }
    }
    __shared__ float sm[256], ss[256];
    sm[tid] = m; ss[tid] = s;
    __syncthreads();
    for (int st = 128; st > 0; st >>= 1) {
        if (tid < st) {
            float m1 = sm[tid], s1 = ss[tid];
            float m2 = sm[tid + st], s2 = ss[tid + st];
            float M = fmaxf(m1, m2);
            float S = ((m1 > -INFINITY) ? s1 * expf(m1 - M) : 0.f) +
                      ((m2 > -INFINITY) ? s2 * expf(m2 - M) : 0.f);
            sm[tid] = M; ss[tid] = S;
        }
        __syncthreads();
    }
    if (tid == 0) {
        float logZ = sm[0] + logf(ss[0]);
        int t = targets[row];
        float lt = logits[(size_t)row * VOCABSZ + t];
        g_rowloss[row] = logZ - lt;
    }
}

__global__ void loss_final_kernel(float* __restrict__ out, int out_size) {
    __shared__ float sm[256];
    const int tid = threadIdx.x;
    float s = 0.f;
    for (int r = tid; r < NT; r += 256) s += g_rowloss[r];
    sm[tid] = s;
    __syncthreads();
    for (int st = 128; st > 0; st >>= 1) {
        if (tid < st) sm[tid] += sm[tid + st];
        __syncthreads();
    }
    if (tid == 0) {
        float loss = sm[0] / (float)NT;
        size_t logits_elems = (size_t)NT * VOCABSZ;
        if ((size_t)out_size > logits_elems) out[logits_elems] = loss;
    }
}

// =========================================================================
extern "C" void kernel_launch(void* const* d_in, const int* in_sizes, int n_in,
                              void* d_out, int out_size) {
    const int*   x       = (const int*)d_in[0];
    const int*   targets = (const int*)d_in[1];
    const float* w_e     = (const float*)d_in[2];
    const float* pos     = (const float*)d_in[3];
    const float* Wq      = (const float*)d_in[4];
    const float* Wk      = (const float*)d_in[5];
    const float* Wv      = (const float*)d_in[6];
    const float* lm_w    = (const float*)d_in[7];
    const float* lm_b    = (const float*)d_in[8];
    float* out = (float*)d_out;

    float *pq, *pk, *pv;
    uint32_t *pblm, *pbqkv;
    cudaGetSymbolAddress((void**)&pq, g_q);
    cudaGetSymbolAddress((void**)&pk, g_k);
    cudaGetSymbolAddress((void**)&pv, g_v);
    cudaGetSymbolAddress((void**)&pblm, g_blm);
    cudaGetSymbolAddress((void**)&pbqkv, g_bqkv);

    cudaFuncSetAttribute(mma_gemm<false>, cudaFuncAttributeMaxDynamicSharedMemorySize, SM_TOTAL);
    cudaFuncSetAttribute(mma_gemm<true>,  cudaFuncAttributeMaxDynamicSharedMemorySize, SM_TOTAL);

    // weight permutations (independent of activations)
    bperm_kernel<<<dim3(NNB, NCHUNK), 256>>>(lm_w, pblm, VOCABSZ);
    bperm_qkv_kernel<<<dim3(3, NCHUNK, 6), 256>>>(Wq, Wk, Wv, pbqkv);

    // embedding + A-perm for layer 0
    embed_perm_kernel<<<dim3(NMB, NCHUNK), 256>>>(x, w_e, pos);

    for (int l = 0; l < 2; l++) {
        uint32_t* bq = pbqkv + (size_t)(l * 3 + 0) * QKV_MAT_U;
        uint32_t* bk = pbqkv + (size_t)(l * 3 + 1) * QKV_MAT_U;
        uint32_t* bv = pbqkv + (size_t)(l * 3 + 2) * QKV_MAT_U;
        mma_gemm<false><<<dim3(NMB, 3, 3), 256, SM_TOTAL>>>(
            bq, bk, bv, pq, pk, pv, nullptr, CDIM);
        attn_kernel<<<(NT / TDIM) * NHEAD, 256>>>();  // updates g_h + g_aperm
    }

    mma_gemm<true><<<dim3(NMB, NNB, 1), 256, SM_TOTAL>>>(
        pblm, pblm, pblm, out, out, out, lm_b, VOCABSZ);

    loss_rows_kernel<<<NT, 256>>>(out, targets);
    loss_final_kernel<<<1, 256>>>(out, out_size);
}

// round 17
// speedup vs baseline: 2.2132x; 1.0086x over previous
#include <cuda_runtime.h>
#include <cuda_fp16.h>
#include <math.h>
#include <stdint.h>

#define NT    2048      // B*T
#define CDIM  384
#define TDIM  32
#define NHEAD 6
#define HEADD 64
#define VOCABSZ 50257
#define TILE_M 128
#define TILE_N 128
#define NMB   16        // NT/128
#define NNB   393       // ceil(VOCAB/128)
#define NCB   786       // stats blocks of 64 cols (2 per CTA N-tile)
#define KCH   32
#define NCHUNK 12       // 384/32
#define NPAIR  6        // chunk pairs
#define CHUNK_U 2048    // u32 (f16x2) per permuted 128x32 chunk
#define NSTAGE 3
#define STAGE_BYTES 32768   // two chunks: [A0 8K|B0 8K|A1 8K|B1 8K]
#define QKV_MAT_U (3 * NCHUNK * CHUNK_U)

// ---- scratch ----
__device__ float g_h[NT * CDIM];
__device__ float g_q[NT * CDIM];
__device__ float g_k[NT * CDIM];
__device__ float g_v[NT * CDIM];
__device__ float g_pmax[NT * NCB];
__device__ float g_psum[NT * NCB];
__device__ float g_rowloss[NT];
__device__ uint32_t g_aperm[NMB * NCHUNK * CHUNK_U];       // 1.5 MB
__device__ uint32_t g_blm[NNB * NCHUNK * CHUNK_U];         // 38.6 MB
__device__ uint32_t g_bqkv[2 * 3 * QKV_MAT_U];             // 1.7 MB

// =========================================================================
// helpers
// =========================================================================
__device__ __forceinline__ uint32_t smem_u32(const void* p) {
    uint32_t a;
    asm("{ .reg .u64 t; cvta.to.shared.u64 t, %1; cvt.u32.u64 %0, t; }" : "=r"(a) : "l"(p));
    return a;
}
__device__ __forceinline__ uint32_t packh2(float x, float y) {
    __half2 h = __floats2half2_rn(x, y);
    return *(uint32_t*)&h;
}
__device__ __forceinline__ void mma_f16(float c[4], const uint32_t a[4], const uint32_t b[2]) {
    asm volatile(
        "mma.sync.aligned.m16n8k16.row.col.f32.f16.f16.f32 "
        "{%0,%1,%2,%3}, {%4,%5,%6,%7}, {%8,%9}, {%0,%1,%2,%3};"
        : "+f"(c[0]), "+f"(c[1]), "+f"(c[2]), "+f"(c[3])
        : "r"(a[0]), "r"(a[1]), "r"(a[2]), "r"(a[3]), "r"(b[0]), "r"(b[1]));
}
#define LDS128(r, addr) \
    asm volatile("ld.shared.v4.b32 {%0,%1,%2,%3}, [%4];" \
        : "=r"((r)[0]), "=r"((r)[1]), "=r"((r)[2]), "=r"((r)[3]) : "r"(addr))
#define LDS64(r, addr) \
    asm volatile("ld.shared.v2.b32 {%0,%1}, [%2];" \
        : "=r"((r)[0]), "=r"((r)[1]) : "r"(addr))
#define CP_ASYNC16(dst, src) \
    asm volatile("cp.async.cg.shared.global [%0], [%1], 16;" :: "r"(dst), "l"(src) : "memory")
#define CP_COMMIT() asm volatile("cp.async.commit_group;" ::: "memory")
#define CP_WAIT1()  asm volatile("cp.async.wait_group 1;" ::: "memory")

// SMEM: bias[128] @0 ; 3 stages of 32KB @1024 ; epilogue stage (128x132 f32) reuses
#define SM_STAGE0 1024
#define SM_TOTAL  (1024 + NSTAGE * STAGE_BYTES)   // 99328

__device__ __forceinline__ int aperm_idx(int r, int k0c) {
    return (((k0c >> 4) * 8 + (r >> 4)) * 32 + (r & 7) * 4 + ((k0c >> 1) & 3)) * 4
           + ((r >> 3) & 1) + 2 * ((k0c >> 3) & 1);
}

__device__ __forceinline__ void compute_chunk(uint32_t Abuf, uint32_t Bbuf,
                                              int wm, int wn, int lid,
                                              float c[2][8][4]) {
#pragma unroll
    for (int ks = 0; ks < 2; ks++) {
        uint32_t a[2][4];
#pragma unroll
        for (int r = 0; r < 2; r++)
            LDS128(a[r], Abuf + ((ks * 8 + wm * 2 + r) * 32 + lid) * 16);
        uint32_t b[8][2];
#pragma unroll
        for (int nf = 0; nf < 8; nf++)
            LDS64(b[nf], Bbuf + ((ks * 16 + wn * 8 + nf) * 32 + lid) * 8);
#pragma unroll
        for (int r = 0; r < 2; r++)
#pragma unroll
            for (int nf = 0; nf < 8; nf++)
                mma_f16(c[r][nf], a[r], b[nf]);
    }
}

__device__ __forceinline__ void supd(float& m, float& s, float v) {
    if (v > m) { s = s * __expf(m - v) + 1.f; m = v; }
    else       { s += __expf(v - m); }
}

// =========================================================================
// Fused embedding + A-permutation
// =========================================================================
__global__ void embed_perm_kernel(const int* __restrict__ x,
                                  const float* __restrict__ w_e,
                                  const float* __restrict__ pos) {
    __shared__ uint32_t sbuf[CHUNK_U];
    const int tid = threadIdx.x;
    const int mb = blockIdx.x, kc = blockIdx.y;
    const int rb = tid >> 3, j = tid & 7;
#pragma unroll
    for (int i = 0; i < 4; i++) {
        int r = i * 32 + rb;
        int m = mb * 128 + r;
        int tok = x[m];
        const float* we = w_e + (size_t)tok * CDIM + kc * KCH + j * 4;
        const float* pp = pos + (size_t)(m & (TDIM - 1)) * CDIM + kc * KCH + j * 4;
        float4 v;
        v.x = we[0] + pp[0]; v.y = we[1] + pp[1];
        v.z = we[2] + pp[2]; v.w = we[3] + pp[3];
        *(float4*)&g_h[(size_t)m * CDIM + kc * KCH + j * 4] = v;
#pragma unroll
        for (int p = 0; p < 2; p++) {
            int k0 = j * 4 + 2 * p;
            sbuf[aperm_idx(r, k0)] = packh2(p ? v.z : v.x, p ? v.w : v.y);
        }
    }
    __syncthreads();
    uint32_t* out = g_aperm + ((size_t)mb * NCHUNK + kc) * CHUNK_U;
#pragma unroll
    for (int i = 0; i < 2; i++)
        *(uint4*)(out + i * 1024 + tid * 4) = *(const uint4*)&sbuf[i * 1024 + tid * 4];
}

// =========================================================================
// B-permutation kernels
// =========================================================================
__global__ void bperm_kernel(const float* __restrict__ B,
                             uint32_t* __restrict__ O, int Ntot) {
    __shared__ uint32_t sbuf[CHUNK_U];
    const int tid = threadIdx.x;
    const int nb = blockIdx.x, kc = blockIdx.y;
    const int rb = tid >> 3, j = tid & 7;
#pragma unroll
    for (int i = 0; i < 4; i++) {
        int r = i * 32 + rb;
        int n = nb * 128 + r;
        float4 v = (n < Ntot) ? *(const float4*)(B + (size_t)n * CDIM + kc * KCH + j * 4)
                              : make_float4(0.f, 0.f, 0.f, 0.f);
#pragma unroll
        for (int p = 0; p < 2; p++) {
            int k0 = j * 4 + 2 * p;
            int idx = (((k0 >> 4) * 16 + (r >> 3)) * 32 + (r & 7) * 4 + ((k0 >> 1) & 3)) * 2
                      + ((k0 >> 3) & 1);
            sbuf[idx] = packh2(p ? v.z : v.x, p ? v.w : v.y);
        }
    }
    __syncthreads();
    uint32_t* out = O + ((size_t)nb * NCHUNK + kc) * CHUNK_U;
#pragma unroll
    for (int i = 0; i < 2; i++)
        *(uint4*)(out + i * 1024 + tid * 4) = *(const uint4*)&sbuf[i * 1024 + tid * 4];
}

// all 6 QKV weight matrices in one launch: grid (3, NCHUNK, 6), z = l*3+mat
__global__ void bperm_qkv_kernel(const float* __restrict__ Wq,
                                 const float* __restrict__ Wk,
                                 const float* __restrict__ Wv,
                                 uint32_t* __restrict__ Oall) {
    __shared__ uint32_t sbuf[CHUNK_U];
    const int tid = threadIdx.x;
    const int nb = blockIdx.x, kc = blockIdx.y, z = blockIdx.z;
    const int l = z / 3, mat = z % 3;
    const size_t wstride = (size_t)NHEAD * HEADD * CDIM;
    const float* B = ((mat == 0) ? Wq : (mat == 1) ? Wk : Wv) + l * wstride;
    uint32_t* O = Oall + (size_t)z * QKV_MAT_U;
    const int rb = tid >> 3, j = tid & 7;
#pragma unroll
    for (int i = 0; i < 4; i++) {
        int r = i * 32 + rb;
        float4 v = *(const float4*)(B + (size_t)(nb * 128 + r) * CDIM + kc * KCH + j * 4);
#pragma unroll
        for (int p = 0; p < 2; p++) {
            int k0 = j * 4 + 2 * p;
            int idx = (((k0 >> 4) * 16 + (r >> 3)) * 32 + (r & 7) * 4 + ((k0 >> 1) & 3)) * 2
                      + ((k0 >> 3) & 1);
            sbuf[idx] = packh2(p ? v.z : v.x, p ? v.w : v.y);
        }
    }
    __syncthreads();
    uint32_t* out = O + ((size_t)nb * NCHUNK + kc) * CHUNK_U;
#pragma unroll
    for (int i = 0; i < 2; i++)
        *(uint4*)(out + i * 1024 + tid * 4) = *(const uint4*)&sbuf[i * 1024 + tid * 4];
}

// =========================================================================
// fp16 tensor GEMM over pre-permuted operands. 128x128 tile, 256 threads.
// (at HMMA issue floor — unchanged)
// =========================================================================
template <bool STATS>
__global__ __launch_bounds__(256)
void mma_gemm(const uint32_t* __restrict__ Bp0, const uint32_t* __restrict__ Bp1,
              const uint32_t* __restrict__ Bp2,
              float* __restrict__ C0, float* __restrict__ C1, float* __restrict__ C2,
              const float* __restrict__ bias, int Ntot) {
    extern __shared__ __align__(1024) char smem[];
    const int tid = threadIdx.x;
    const int lid = tid & 31, wid = tid >> 5;
    const int wm = wid >> 1, wn = wid & 1;
    const int bm = blockIdx.x * TILE_M;
    const int bn = blockIdx.y * TILE_N;
    const uint32_t* Bperm = (blockIdx.z == 0) ? Bp0 : (blockIdx.z == 1 ? Bp1 : Bp2);
    float* C = (blockIdx.z == 0) ? C0 : (blockIdx.z == 1 ? C1 : C2);

    const uint32_t* Ac = g_aperm + (size_t)blockIdx.x * NCHUNK * CHUNK_U;
    const uint32_t* Bc = Bperm + (size_t)blockIdx.y * NCHUNK * CHUNK_U;

    float* biasS = (float*)smem;
    float* stage = (float*)(smem + SM_STAGE0);
    const uint32_t sb = smem_u32(smem);

    if (tid < TILE_N) {
        int n = bn + tid;
        biasS[tid] = (bias != nullptr && n < Ntot) ? bias[n] : 0.f;
    }

    float c[2][8][4];
#pragma unroll
    for (int r = 0; r < 2; r++)
#pragma unroll
        for (int nf = 0; nf < 8; nf++)
#pragma unroll
            for (int e = 0; e < 4; e++) c[r][nf][e] = 0.f;

    auto issue_pair = [&](int kp, int s) {
        uint32_t base = sb + SM_STAGE0 + s * STAGE_BYTES + tid * 16;
#pragma unroll
        for (int u = 0; u < 2; u++) {
            const uint32_t* srcA = Ac + (size_t)(2 * kp + u) * CHUNK_U + tid * 4;
            const uint32_t* srcB = Bc + (size_t)(2 * kp + u) * CHUNK_U + tid * 4;
            CP_ASYNC16(base + u * 16384, srcA);
            CP_ASYNC16(base + u * 16384 + 4096, srcA + 1024);
            CP_ASYNC16(base + u * 16384 + 8192, srcB);
            CP_ASYNC16(base + u * 16384 + 12288, srcB + 1024);
        }
    };

    issue_pair(0, 0); CP_COMMIT();
    issue_pair(1, 1); CP_COMMIT();

    for (int kp = 0; kp < NPAIR; kp++) {
        CP_WAIT1();
        __syncthreads();
        if (kp + 2 < NPAIR) issue_pair(kp + 2, (kp + 2) % NSTAGE);
        CP_COMMIT();
        const uint32_t base = sb + SM_STAGE0 + (kp % NSTAGE) * STAGE_BYTES;
        compute_chunk(base, base + 8192, wm, wn, lid, c);
        compute_chunk(base + 16384, base + 24576, wm, wn, lid, c);
    }
    __syncthreads();

    const int g = lid >> 2, t4 = lid & 3;
    const bool full = (bn + TILE_N <= Ntot);

#pragma unroll
    for (int r = 0; r < 2; r++)
#pragma unroll
        for (int nf = 0; nf < 8; nf++) {
            const int col = wn * 64 + nf * 8 + t4 * 2;
            const float b0 = biasS[col], b1 = biasS[col + 1];
            c[r][nf][0] += b0; c[r][nf][1] += b1;
            c[r][nf][2] += b0; c[r][nf][3] += b1;
        }

    if (STATS) {
        float rm[2][2], rs[2][2];
#pragma unroll
        for (int r = 0; r < 2; r++)
#pragma unroll
            for (int h = 0; h < 2; h++) { rm[r][h] = -INFINITY; rs[r][h] = 0.f; }
        if (full) {
#pragma unroll
            for (int r = 0; r < 2; r++)
#pragma unroll
                for (int nf = 0; nf < 8; nf++) {
                    rm[r][0] = fmaxf(rm[r][0], fmaxf(c[r][nf][0], c[r][nf][1]));
                    rm[r][1] = fmaxf(rm[r][1], fmaxf(c[r][nf][2], c[r][nf][3]));
                }
#pragma unroll
            for (int r = 0; r < 2; r++)
#pragma unroll
                for (int nf = 0; nf < 8; nf++) {
                    rs[r][0] += __expf(c[r][nf][0] - rm[r][0]) +
                                __expf(c[r][nf][1] - rm[r][0]);
                    rs[r][1] += __expf(c[r][nf][2] - rm[r][1]) +
                                __expf(c[r][nf][3] - rm[r][1]);
                }
        } else {
#pragma unroll
            for (int r = 0; r < 2; r++)
#pragma unroll
                for (int nf = 0; nf < 8; nf++) {
                    const int n = bn + wn * 64 + nf * 8 + t4 * 2;
                    if (n < Ntot)     { supd(rm[r][0], rs[r][0], c[r][nf][0]);
                                        supd(rm[r][1], rs[r][1], c[r][nf][2]); }
                    if (n + 1 < Ntot) { supd(rm[r][0], rs[r][0], c[r][nf][1]);
                                        supd(rm[r][1], rs[r][1], c[r][nf][3]); }
                }
        }
#pragma unroll
        for (int r = 0; r < 2; r++)
#pragma unroll
            for (int h = 0; h < 2; h++) {
                float m = rm[r][h], s = rs[r][h];
#pragma unroll
                for (int off = 1; off <= 2; off <<= 1) {
                    float om = __shfl_xor_sync(0xffffffffu, m, off);
                    float os = __shfl_xor_sync(0xffffffffu, s, off);
                    float M = fmaxf(m, om);
                    float S = ((m > -INFINITY) ? s * __expf(m - M) : 0.f) +
                              ((om > -INFINITY) ? os * __expf(om - M) : 0.f);
                    m = M; s = S;
                }
                if (t4 == 0) {
                    int mrow = bm + wm * 32 + r * 16 + h * 8 + g;
                    size_t idx = (size_t)mrow * NCB + blockIdx.y * 2 + wn;
                    g_pmax[idx] = m;
                    g_psum[idx] = s;
                }
            }
    }

#pragma unroll
    for (int r = 0; r < 2; r++) {
        const int row = wm * 32 + r * 16 + g;
#pragma unroll
        for (int nf = 0; nf < 8; nf++) {
            const int col = wn * 64 + nf * 8 + t4 * 2;
            *(float2*)&stage[row * 132 + col] = make_float2(c[r][nf][0], c[r][nf][1]);
            *(float2*)&stage[(row + 8) * 132 + col] = make_float2(c[r][nf][2], c[r][nf][3]);
        }
    }
    __syncthreads();
    if (full) {
#pragma unroll 8
        for (int it = 0; it < 64; it++) {
            int idx = it * 256 + tid;
            int rr = idx >> 7, cc = idx & 127;
            C[(size_t)(bm + rr) * Ntot + bn + cc] = stage[rr * 132 + cc];
        }
    } else {
#pragma unroll 8
        for (int it = 0; it < 64; it++) {
            int idx = it * 256 + tid;
            int rr = idx >> 7, cc = idx & 127;
            int n = bn + cc;
            if (n < Ntot) C[(size_t)(bm + rr) * Ntot + n] = stage[rr * 132 + cc];
        }
    }
}

// =========================================================================
// Attention — updates g_h AND writes permuted fp16 chunks
// =========================================================================
__global__ void attn_kernel() {
    __shared__ float qs[32][65];
    __shared__ float ks[32][65];
    __shared__ float vs[32][65];
    __shared__ float w[32][33];

    const int bh = blockIdx.x;
    const int b = bh / NHEAD, hd = bh % NHEAD;
    const int tid = threadIdx.x;
    const int base = (b * TDIM) * CDIM + hd * HEADD;

    for (int i = tid; i < 32 * 64; i += 256) {
        int t = i >> 6, d = i & 63;
        int g = base + t * CDIM + d;
        qs[t][d] = g_q[g];
        ks[t][d] = g_k[g];
        vs[t][d] = g_v[g];
    }
    __syncthreads();

    const float scale = 0.125f;
    for (int i = tid; i < 32 * 32; i += 256) {
        int t = i >> 5, s = i & 31;
        float v = -INFINITY;
        if (s <= t) {
            float acc = 0.f;
#pragma unroll
            for (int d = 0; d < 64; d++) acc += qs[t][d] * ks[s][d];
            v = acc * scale;
        }
        w[t][s] = v;
    }
    __syncthreads();

    if (tid < 32) {
        int t = tid;
        float mx = -INFINITY;
        for (int s = 0; s <= t; s++) mx = fmaxf(mx, w[t][s]);
        float sum = 0.f;
        for (int s = 0; s <= t; s++) { float e = expf(w[t][s] - mx); w[t][s] = e; sum += e; }
        float inv = 1.f / sum;
        for (int s = 0; s <= t; s++) w[t][s] *= inv;
        for (int s = t + 1; s < 32; s++) w[t][s] = 0.f;
    }
    __syncthreads();

    for (int i = tid; i < 32 * 32; i += 256) {
        int t = i >> 5, d0 = (i & 31) * 2;
        float a0 = 0.f, a1 = 0.f;
#pragma unroll
        for (int s = 0; s < 32; s++) {
            a0 += w[t][s] * vs[s][d0];
            a1 += w[t][s] * vs[s][d0 + 1];
        }
        const int off = base + t * CDIM + d0;
        float2 hv = *(float2*)&g_h[off];
        hv.x += a0; hv.y += a1;
        *(float2*)&g_h[off] = hv;
        const int m = b * TDIM + t;
        const int k0 = hd * HEADD + d0;
        const int kc = k0 >> 5, k0c = k0 & 31;
        g_aperm[((size_t)(m >> 7) * NCHUNK + kc) * CHUNK_U + aperm_idx(m & 127, k0c)] =
            packh2(hv.x, hv.y);
    }
}

// =========================================================================
// Loss
// =========================================================================
__global__ void loss_rows_kernel(const float* __restrict__ logits,
                                 const int* __restrict__ targets) {
    const int row = blockIdx.x;
    const int tid = threadIdx.x;
    float m = -INFINITY, s = 0.f;
    for (int cb = tid; cb < NCB; cb += 256) {
        float mi = g_pmax[(size_t)row * NCB + cb];
        float si = g_psum[(size_t)row * NCB + cb];
        if (mi > m) { s = s * expf(m - mi) + si; m = mi; }
        else if (mi > -INFINITY) { s += si * expf(mi - m); }
    }
    __shared__ float sm[256], ss[256];
    sm[tid] = m; ss[tid] = s;
    __syncthreads();
    for (int st = 128; st > 0; st >>= 1) {
        if (tid < st) {
            float m1 = sm[tid], s1 = ss[tid];
            float m2 = sm[tid + st], s2 = ss[tid + st];
            float M = fmaxf(m1, m2);
            float S = ((m1 > -INFINITY) ? s1 * expf(m1 - M) : 0.f) +
                      ((m2 > -INFINITY) ? s2 * expf(m2 - M) : 0.f);
            sm[tid] = M; ss[tid] = S;
        }
        __syncthreads();
    }
    if (tid == 0) {
        float logZ = sm[0] + logf(ss[0]);
        int t = targets[row];
        float lt = logits[(size_t)row * VOCABSZ + t];
        g_rowloss[row] = logZ - lt;
    }
}

__global__ void loss_final_kernel(float* __restrict__ out, int out_size) {
    __shared__ float sm[256];
    const int tid = threadIdx.x;
    float s = 0.f;
    for (int r = tid; r < NT; r += 256) s += g_rowloss[r];
    sm[tid] = s;
    __syncthreads();
    for (int st = 128; st > 0; st >>= 1) {
        if (tid < st) sm[tid] += sm[tid + st];
        __syncthreads();
    }
    if (tid == 0) {
        float loss = sm[0] / (float)NT;
        size_t logits_elems = (size_t)NT * VOCABSZ;
        if ((size_t)out_size > logits_elems) out[logits_elems] = loss;
    }
}

// =========================================================================
extern "C" void kernel_launch(void* const* d_in, const int* in_sizes, int n_in,
                              void* d_out, int out_size) {
    const int*   x       = (const int*)d_in[0];
    const int*   targets = (const int*)d_in[1];
    const float* w_e     = (const float*)d_in[2];
    const float* pos     = (const float*)d_in[3];
    const float* Wq      = (const float*)d_in[4];
    const float* Wk      = (const float*)d_in[5];
    const float* Wv      = (const float*)d_in[6];
    const float* lm_w    = (const float*)d_in[7];
    const float* lm_b    = (const float*)d_in[8];
    float* out = (float*)d_out;

    float *pq, *pk, *pv;
    uint32_t *pblm, *pbqkv;
    cudaGetSymbolAddress((void**)&pq, g_q);
    cudaGetSymbolAddress((void**)&pk, g_k);
    cudaGetSymbolAddress((void**)&pv, g_v);
    cudaGetSymbolAddress((void**)&pblm, g_blm);
    cudaGetSymbolAddress((void**)&pbqkv, g_bqkv);

    cudaFuncSetAttribute(mma_gemm<false>, cudaFuncAttributeMaxDynamicSharedMemorySize, SM_TOTAL);
    cudaFuncSetAttribute(mma_gemm<true>,  cudaFuncAttributeMaxDynamicSharedMemorySize, SM_TOTAL);

    // ---- fork: lm_w permutation runs concurrently with the attention chain ----
    cudaStream_t s2;
    cudaEvent_t evFork, evJoin;
    cudaStreamCreateWithFlags(&s2, cudaStreamNonBlocking);
    cudaEventCreateWithFlags(&evFork, cudaEventDisableTiming);
    cudaEventCreateWithFlags(&evJoin, cudaEventDisableTiming);

    cudaEventRecord(evFork, 0);
    cudaStreamWaitEvent(s2, evFork, 0);
    bperm_kernel<<<dim3(NNB, NCHUNK), 256, 0, s2>>>(lm_w, pblm, VOCABSZ);
    cudaEventRecord(evJoin, s2);

    // main stream: weights + embedding + attention chain
    bperm_qkv_kernel<<<dim3(3, NCHUNK, 6), 256>>>(Wq, Wk, Wv, pbqkv);
    embed_perm_kernel<<<dim3(NMB, NCHUNK), 256>>>(x, w_e, pos);

    for (int l = 0; l < 2; l++) {
        uint32_t* bq = pbqkv + (size_t)(l * 3 + 0) * QKV_MAT_U;
        uint32_t* bk = pbqkv + (size_t)(l * 3 + 1) * QKV_MAT_U;
        uint32_t* bv = pbqkv + (size_t)(l * 3 + 2) * QKV_MAT_U;
        mma_gemm<false><<<dim3(NMB, 3, 3), 256, SM_TOTAL>>>(
            bq, bk, bv, pq, pk, pv, nullptr, CDIM);
        attn_kernel<<<(NT / TDIM) * NHEAD, 256>>>();
    }

    // join: logits gemm needs permuted lm_w
    cudaStreamWaitEvent(0, evJoin, 0);
    mma_gemm<true><<<dim3(NMB, NNB, 1), 256, SM_TOTAL>>>(
        pblm, pblm, pblm, out, out, out, lm_b, VOCABSZ);

    loss_rows_kernel<<<NT, 256>>>(out, targets);
    loss_final_kernel<<<1, 256>>>(out, out_size);

    cudaEventDestroy(evFork);
    cudaEventDestroy(evJoin);
    cudaStreamDestroy(s2);
}